// round 16
// baseline (speedup 1.0000x reference)
#include <cuda_runtime.h>
#include <cuda_fp16.h>
#include <cstdint>

// Problem constants
#define NNODES 50000
#define NEDGES 800000
#define IN_C   256
#define OUT_C  128
#define NB3    25            // scan blocks: 25 * 2048 = 51200 >= NNODES
#define RB     391           // rank blocks: 391 * 256 * 8 >= NEDGES
#define FILLB  1563          // fill blocks: 1563 * 256 * 2 >= NEDGES

// Scratch
__device__ __align__(16) __half g_y[NNODES * OUT_C];  // linear output, fp16
__device__ __align__(16) int g_deg[NNODES];           // zero at entry (consumer-reset)
__device__ __align__(16) int g_off[NNODES + 1];
__device__ __align__(16) int g_rank[NEDGES];
__device__ int g_srcs[NEDGES];
// decoupled-lookback scan state; zero at entry (fill phase resets)
__device__ int g_blk_state[NB3];
__device__ int g_blk_agg[NB3];
__device__ int g_blk_pref[NB3];
// phase flags; zero at entry (gather resets)
__device__ int g_done1;
__device__ int g_done2;

// ---------------------------------------------------------------------------
// K1: fused build — rank (atomic pass) -> scan (lookback) -> fill.
// Phase barriers via done-counters; waited-on block sets are prefixes of the
// resident wave (391 and 25 blocks, both << 6/SM * 148 = 888 resident).
// ---------------------------------------------------------------------------
__global__ __launch_bounds__(256, 6) void build_kernel(const int* __restrict__ ei) {
    const int bid = blockIdx.x;
    const int tid = threadIdx.x;
    const int t = bid * 256 + tid;
    const int lane = tid & 31, wid = tid >> 5;

    // ---------------- Phase 1: rank (blocks 0..RB-1, 8 edges/thread)
    if (bid < RB) {
        int base = t * 8;
        if (base < NEDGES) {
            int4 d0 = *reinterpret_cast<const int4*>(ei + NEDGES + base);
            int4 d1 = *reinterpret_cast<const int4*>(ei + NEDGES + base + 4);
            int4 r0, r1;
            r0.x = atomicAdd(&g_deg[d0.x], 1);
            r0.y = atomicAdd(&g_deg[d0.y], 1);
            r0.z = atomicAdd(&g_deg[d0.z], 1);
            r0.w = atomicAdd(&g_deg[d0.w], 1);
            r1.x = atomicAdd(&g_deg[d1.x], 1);
            r1.y = atomicAdd(&g_deg[d1.y], 1);
            r1.z = atomicAdd(&g_deg[d1.z], 1);
            r1.w = atomicAdd(&g_deg[d1.w], 1);
            *reinterpret_cast<int4*>(&g_rank[base]) = r0;
            *reinterpret_cast<int4*>(&g_rank[base + 4]) = r1;
        }
        __syncthreads();
        if (tid == 0) { __threadfence(); atomicAdd(&g_done1, 1); }
    }

    // ---------------- Phase 2: scan (blocks 0..NB3-1)
    if (bid < NB3) {
        if (tid == 0) {
            volatile int* p = &g_done1;
            while (*p != RB) __nanosleep(128);
        }
        __syncthreads();
        __threadfence();

        __shared__ int ws[8];
        __shared__ int s_excl;
        const int e0 = (bid * 256 + tid) * 8;
        const bool inb0 = (e0 < NNODES);

        int4 da = inb0 ? __ldcg(reinterpret_cast<const int4*>(&g_deg[e0]))
                       : make_int4(0, 0, 0, 0);
        int4 db = inb0 ? __ldcg(reinterpret_cast<const int4*>(&g_deg[e0 + 4]))
                       : make_int4(0, 0, 0, 0);
        if (inb0) {
            *reinterpret_cast<int4*>(&g_deg[e0]) = make_int4(0, 0, 0, 0);
            *reinterpret_cast<int4*>(&g_deg[e0 + 4]) = make_int4(0, 0, 0, 0);
        }
        int p0 = da.x;
        int p1 = p0 + da.y;
        int p2 = p1 + da.z;
        int p3 = p2 + da.w;
        int p4 = p3 + db.x;
        int p5 = p4 + db.y;
        int p6 = p5 + db.z;
        int p7 = p6 + db.w;

        int incl = p7;
        #pragma unroll
        for (int dd = 1; dd < 32; dd <<= 1) {
            int u = __shfl_up_sync(0xffffffffu, incl, dd);
            if (lane >= dd) incl += u;
        }
        if (lane == 31) ws[wid] = incl;
        __syncthreads();
        if (wid == 0) {
            int s = (lane < 8) ? ws[lane] : 0;
            #pragma unroll
            for (int dd = 1; dd < 8; dd <<= 1) {
                int u = __shfl_up_sync(0xffffffffu, s, dd);
                if (lane >= dd) s += u;
            }
            if (lane < 8) ws[lane] = s;
        }
        __syncthreads();
        int thr_excl = incl - p7 + (wid > 0 ? ws[wid - 1] : 0);
        int total = ws[7];

        if (tid == 0) {
            if (bid == 0) {
                g_blk_pref[0] = total;
                __threadfence();
                atomicExch(&g_blk_state[0], 2);
            } else {
                g_blk_agg[bid] = total;
                __threadfence();
                atomicExch(&g_blk_state[bid], 1);
            }
        }
        if (wid == 0) {
            int excl = 0;
            if (bid > 0) {
                int hi_end = bid;
                while (hi_end > 0) {
                    int start = hi_end - 32 > 0 ? hi_end - 32 : 0;
                    int idx = start + lane;
                    bool valid = (idx < hi_end);
                    int st = 2;
                    do {
                        if (valid) st = atomicAdd(&g_blk_state[idx], 0);
                    } while (__any_sync(0xffffffffu, valid && st == 0));
                    int val = 0;
                    if (valid)
                        val = (st == 2) ? atomicAdd(&g_blk_pref[idx], 0)
                                        : atomicAdd(&g_blk_agg[idx], 0);
                    unsigned m2 = __ballot_sync(0xffffffffu, valid && st == 2);
                    int contrib;
                    bool done;
                    if (m2) {
                        int hi = 31 - __clz(m2);
                        contrib = (valid && lane >= hi) ? val : 0;
                        done = true;
                    } else {
                        contrib = valid ? val : 0;
                        done = false;
                    }
                    #pragma unroll
                    for (int dd = 16; dd > 0; dd >>= 1)
                        contrib += __shfl_down_sync(0xffffffffu, contrib, dd);
                    excl += __shfl_sync(0xffffffffu, contrib, 0);
                    if (done) break;
                    hi_end = start;
                }
                if (lane == 0) {
                    g_blk_pref[bid] = excl + total;
                    __threadfence();
                    atomicExch(&g_blk_state[bid], 2);
                }
            }
            if (lane == 0) s_excl = excl;
        }
        __syncthreads();

        if (inb0) {
            int base = s_excl + thr_excl;
            int4 oa = make_int4(base, base + p0, base + p1, base + p2);
            int4 ob = make_int4(base + p3, base + p4, base + p5, base + p6);
            *reinterpret_cast<int4*>(&g_off[e0]) = oa;
            *reinterpret_cast<int4*>(&g_off[e0 + 4]) = ob;
        }
        if (bid == 0 && tid == 0) g_off[NNODES] = NEDGES;

        __syncthreads();
        if (tid == 0) { __threadfence(); atomicAdd(&g_done2, 1); }
    }

    // ---------------- Phase 3: fill (all blocks, 2 edges/thread)
    if (tid == 0) {
        volatile int* p = &g_done2;
        while (*p != NB3) __nanosleep(128);
    }
    __syncthreads();
    __threadfence();

    if (bid == 0 && tid < NB3) g_blk_state[tid] = 0;   // reset for next call

    {
        int base = t * 2;
        if (base < NEDGES) {
            int2 s = *reinterpret_cast<const int2*>(ei + base);
            int2 d = *reinterpret_cast<const int2*>(ei + NEDGES + base);
            int2 r = *reinterpret_cast<const int2*>(&g_rank[base]);
            int o0 = __ldcg(&g_off[d.x]);
            int o1 = __ldcg(&g_off[d.y]);
            g_srcs[o0 + r.x] = s.x;
            g_srcs[o1 + r.y] = s.y;
        }
    }
}

// ---------------------------------------------------------------------------
// K2: fp16 tensor-core GEMM (m16n8k16, fp32 accum), double-buffered smem.
// y[m,n] = sum_k x[m,k] * W[n,k] + b[n], fp16 out.
// ---------------------------------------------------------------------------
#define GBM 128
#define GBK 16
#define SSTRIDE 136
#define NTILES (IN_C / GBK)   // 16

__device__ __forceinline__ uint32_t pack_h2(float a, float b) {
    __half2 h = __floats2half2_rn(a, b);
    return *reinterpret_cast<uint32_t*>(&h);
}

__global__ __launch_bounds__(256, 2) void gemm_fp16_kernel(
    const float* __restrict__ x,
    const float* __restrict__ W,
    const float* __restrict__ b)
{
    __shared__ uint32_t As[2][8 * SSTRIDE];
    __shared__ uint32_t Bs[2][8 * SSTRIDE];

    const int tid  = threadIdx.x;
    const int lane = tid & 31;
    const int warp = tid >> 5;
    const int wm   = warp >> 1;
    const int wn   = warp & 1;
    const int block_m = blockIdx.x * GBM;
    const int grp = lane >> 2;
    const int qid = lane & 3;

    const int idx0 = tid * 2;
    const int row0 = idx0 >> 2;
    const int kq0  = (idx0 & 3) * 4;
    const int row1 = (idx0 + 1) >> 2;
    const int kq1  = ((idx0 + 1) & 3) * 4;
    const int gm0 = block_m + row0;
    const int gm1 = block_m + row1;
    const bool ok0 = (gm0 < NNODES);
    const bool ok1 = (gm1 < NNODES);

    float acc[2][8][4];
    #pragma unroll
    for (int i = 0; i < 2; i++)
        #pragma unroll
        for (int j = 0; j < 8; j++)
            #pragma unroll
            for (int c = 0; c < 4; c++)
                acc[i][j][c] = 0.f;

    float4 pa0, pa1, pb0, pb1;

    pa0 = ok0 ? *reinterpret_cast<const float4*>(x + (size_t)gm0 * IN_C + kq0)
              : make_float4(0.f, 0.f, 0.f, 0.f);
    pa1 = ok1 ? *reinterpret_cast<const float4*>(x + (size_t)gm1 * IN_C + kq1)
              : make_float4(0.f, 0.f, 0.f, 0.f);
    pb0 = *reinterpret_cast<const float4*>(W + (size_t)row0 * IN_C + kq0);
    pb1 = *reinterpret_cast<const float4*>(W + (size_t)row1 * IN_C + kq1);

    {
        As[0][((kq0 >> 1) + 0) * SSTRIDE + row0] = pack_h2(pa0.x, pa0.y);
        As[0][((kq0 >> 1) + 1) * SSTRIDE + row0] = pack_h2(pa0.z, pa0.w);
        As[0][((kq1 >> 1) + 0) * SSTRIDE + row1] = pack_h2(pa1.x, pa1.y);
        As[0][((kq1 >> 1) + 1) * SSTRIDE + row1] = pack_h2(pa1.z, pa1.w);
        Bs[0][((kq0 >> 1) + 0) * SSTRIDE + row0] = pack_h2(pb0.x, pb0.y);
        Bs[0][((kq0 >> 1) + 1) * SSTRIDE + row0] = pack_h2(pb0.z, pb0.w);
        Bs[0][((kq1 >> 1) + 0) * SSTRIDE + row1] = pack_h2(pb1.x, pb1.y);
        Bs[0][((kq1 >> 1) + 1) * SSTRIDE + row1] = pack_h2(pb1.z, pb1.w);
    }
    __syncthreads();

    for (int t = 0; t < NTILES; t++) {
        const int cur = t & 1;
        const bool has_next = (t + 1 < NTILES);

        if (has_next) {
            int k0 = (t + 1) * GBK;
            pa0 = ok0 ? *reinterpret_cast<const float4*>(x + (size_t)gm0 * IN_C + k0 + kq0)
                      : make_float4(0.f, 0.f, 0.f, 0.f);
            pa1 = ok1 ? *reinterpret_cast<const float4*>(x + (size_t)gm1 * IN_C + k0 + kq1)
                      : make_float4(0.f, 0.f, 0.f, 0.f);
            pb0 = *reinterpret_cast<const float4*>(W + (size_t)row0 * IN_C + k0 + kq0);
            pb1 = *reinterpret_cast<const float4*>(W + (size_t)row1 * IN_C + k0 + kq1);
        }

        {
            uint32_t af[2][4];
            #pragma unroll
            for (int i = 0; i < 2; i++) {
                int rm = wm * 32 + i * 16 + grp;
                af[i][0] = As[cur][qid * SSTRIDE + rm];
                af[i][1] = As[cur][qid * SSTRIDE + rm + 8];
                af[i][2] = As[cur][(qid + 4) * SSTRIDE + rm];
                af[i][3] = As[cur][(qid + 4) * SSTRIDE + rm + 8];
            }
            uint32_t bf[8][2];
            #pragma unroll
            for (int j = 0; j < 8; j++) {
                int bn = wn * 64 + j * 8 + grp;
                bf[j][0] = Bs[cur][qid * SSTRIDE + bn];
                bf[j][1] = Bs[cur][(qid + 4) * SSTRIDE + bn];
            }
            #pragma unroll
            for (int i = 0; i < 2; i++)
                #pragma unroll
                for (int j = 0; j < 8; j++) {
                    asm volatile(
                        "mma.sync.aligned.m16n8k16.row.col.f32.f16.f16.f32 "
                        "{%0,%1,%2,%3}, {%4,%5,%6,%7}, {%8,%9}, {%0,%1,%2,%3};\n"
                        : "+f"(acc[i][j][0]), "+f"(acc[i][j][1]),
                          "+f"(acc[i][j][2]), "+f"(acc[i][j][3])
                        : "r"(af[i][0]), "r"(af[i][1]), "r"(af[i][2]), "r"(af[i][3]),
                          "r"(bf[j][0]), "r"(bf[j][1]));
                }
        }

        if (has_next) {
            const int nxt = cur ^ 1;
            As[nxt][((kq0 >> 1) + 0) * SSTRIDE + row0] = pack_h2(pa0.x, pa0.y);
            As[nxt][((kq0 >> 1) + 1) * SSTRIDE + row0] = pack_h2(pa0.z, pa0.w);
            As[nxt][((kq1 >> 1) + 0) * SSTRIDE + row1] = pack_h2(pa1.x, pa1.y);
            As[nxt][((kq1 >> 1) + 1) * SSTRIDE + row1] = pack_h2(pa1.z, pa1.w);
            Bs[nxt][((kq0 >> 1) + 0) * SSTRIDE + row0] = pack_h2(pb0.x, pb0.y);
            Bs[nxt][((kq0 >> 1) + 1) * SSTRIDE + row0] = pack_h2(pb0.z, pb0.w);
            Bs[nxt][((kq1 >> 1) + 0) * SSTRIDE + row1] = pack_h2(pb1.x, pb1.y);
            Bs[nxt][((kq1 >> 1) + 1) * SSTRIDE + row1] = pack_h2(pb1.z, pb1.w);
            __syncthreads();
        }
    }

    #pragma unroll
    for (int i = 0; i < 2; i++) {
        int r0 = block_m + wm * 32 + i * 16 + grp;
        int r1 = r0 + 8;
        #pragma unroll
        for (int j = 0; j < 8; j++) {
            int col = wn * 64 + j * 8 + qid * 2;
            float b0 = b[col], b1 = b[col + 1];
            if (r0 < NNODES) {
                __half2 h = __floats2half2_rn(acc[i][j][0] + b0, acc[i][j][1] + b1);
                *reinterpret_cast<__half2*>(&g_y[(size_t)r0 * OUT_C + col]) = h;
            }
            if (r1 < NNODES) {
                __half2 h = __floats2half2_rn(acc[i][j][2] + b0, acc[i][j][3] + b1);
                *reinterpret_cast<__half2*>(&g_y[(size_t)r1 * OUT_C + col]) = h;
            }
        }
    }
}

// ---------------------------------------------------------------------------
// K3: gather + mean. ONE node per warp; lane = uint2 (4 halfs; 32 x 8B = one
// 256B row per request). Src ids fetched with ONE coalesced load + shuffle
// broadcast (deg <= 32 covers ~all nodes; scalar fallback beyond).
// Resets the build-phase flags for the next call.
// ---------------------------------------------------------------------------
__device__ __forceinline__ void acc_row4(float* acc, uint2 v) {
    float2 f;
    f = __half22float2(*reinterpret_cast<__half2*>(&v.x)); acc[0] += f.x; acc[1] += f.y;
    f = __half22float2(*reinterpret_cast<__half2*>(&v.y)); acc[2] += f.x; acc[3] += f.y;
}

__global__ __launch_bounds__(256) void gather_kernel(float* __restrict__ out) {
    if (blockIdx.x == 0 && threadIdx.x == 0) { g_done1 = 0; g_done2 = 0; }

    int node = (blockIdx.x * blockDim.x + threadIdx.x) >> 5;
    int lane = threadIdx.x & 31;
    if (node >= NNODES) return;

    int s = g_off[node];
    int e = g_off[node + 1];
    int deg = e - s;
    int m = min(deg, 32);

    // one coalesced load covers all src ids for deg <= 32
    int sn_l = (lane < m) ? __ldg(&g_srcs[s + lane]) : 0;

    float acc[4];
    #pragma unroll
    for (int c = 0; c < 4; c++) acc[c] = 0.f;

    const size_t loff = (size_t)lane * 4;

    int i = 0;
    for (; i + 8 <= m; i += 8) {
        uint2 v[8];
        #pragma unroll
        for (int q = 0; q < 8; q++) {
            int src = __shfl_sync(0xffffffffu, sn_l, i + q);
            v[q] = *reinterpret_cast<const uint2*>(&g_y[(size_t)src * OUT_C + loff]);
        }
        #pragma unroll
        for (int q = 0; q < 8; q++) acc_row4(acc, v[q]);
    }
    for (; i < m; i++) {
        int src = __shfl_sync(0xffffffffu, sn_l, i);
        uint2 v = *reinterpret_cast<const uint2*>(&g_y[(size_t)src * OUT_C + loff]);
        acc_row4(acc, v);
    }
    for (int j = s + 32; j < e; j++) {   // rare tail (deg > 32)
        int src = __ldg(&g_srcs[j]);
        uint2 v = *reinterpret_cast<const uint2*>(&g_y[(size_t)src * OUT_C + loff]);
        acc_row4(acc, v);
    }

    float inv = 1.0f / (float)max(deg, 1);
    float4 o = make_float4(acc[0] * inv, acc[1] * inv, acc[2] * inv, acc[3] * inv);
    *reinterpret_cast<float4*>(&out[(size_t)node * OUT_C + loff]) = o;
}

// ---------------------------------------------------------------------------
extern "C" void kernel_launch(void* const* d_in, const int* in_sizes, int n_in,
                              void* d_out, int out_size) {
    const float* x  = (const float*)d_in[0];
    const int*   ei = (const int*)d_in[1];
    const float* W  = (const float*)d_in[2];
    const float* b  = (const float*)d_in[3];
    float* out = (float*)d_out;

    static cudaStream_t s_gemm = nullptr;
    static cudaEvent_t ev_fork = nullptr, ev_join = nullptr;
    if (!s_gemm) {
        cudaStreamCreateWithFlags(&s_gemm, cudaStreamNonBlocking);
        cudaEventCreateWithFlags(&ev_fork, cudaEventDisableTiming);
        cudaEventCreateWithFlags(&ev_join, cudaEventDisableTiming);
    }

    // Fork: GEMM on side stream (independent of CSR build)
    cudaEventRecord(ev_fork, 0);
    cudaStreamWaitEvent(s_gemm, ev_fork, 0);
    gemm_fp16_kernel<<<(NNODES + GBM - 1) / GBM, 256, 0, s_gemm>>>(x, W, b);
    cudaEventRecord(ev_join, s_gemm);

    // Fused CSR build on main stream (g_deg, g_blk_state, flags zero at entry)
    build_kernel<<<FILLB, 256>>>(ei);

    // Join, then gather + mean (one warp per node)
    cudaStreamWaitEvent(0, ev_join, 0);
    gather_kernel<<<(NNODES * 32 + 255) / 256, 256>>>(out);
}